// round 8
// baseline (speedup 1.0000x reference)
#include <cuda_runtime.h>

// y = exp(i * LZ * DPHI) * x, elementwise.
// ifft2(fft2(x) * scalar) == scalar * x by linearity of the FFT.
// LZ*DPHI = 0.05 -> c = cos(0.05) + i*sin(0.05)
//
// Inputs:  d_in[0] = x_real [B*M*N] f32, d_in[1] = x_imag [B*M*N] f32
// Output:  d_out [2*B*M*N] f32, first half = real(y), second half = imag(y)
//
// CONVERGED CONFIG. Pure HBM-bound stream (256 MB read + 256 MB write,
// zero reuse) at 6.54 TB/s = the measured B300 mixed R/W DRAM ceiling.
// Block-size sweep: 512:75.6 / 256:74.5 / 128:73.9 / 64:76.4 us -> 128 wins.
// Persistence, deeper MLP, and .cs cache policies all tested: neutral or
// regressed. Grid exactly tiles n4 (n is a power of two), so no bounds check.

#define COS_C 0.9987502603949663f
#define SIN_C 0.0499791692706783f

__global__ void __launch_bounds__(128, 16)
freq_shift_kernel(const float4* __restrict__ xr,
                  const float4* __restrict__ xi,
                  float4* __restrict__ yr,
                  float4* __restrict__ yi)
{
    int i = blockIdx.x * blockDim.x + threadIdx.x;

    float4 r = xr[i];
    float4 m = xi[i];

    float4 orr, oii;
    orr.x = fmaf(r.x, COS_C, -m.x * SIN_C);
    orr.y = fmaf(r.y, COS_C, -m.y * SIN_C);
    orr.z = fmaf(r.z, COS_C, -m.z * SIN_C);
    orr.w = fmaf(r.w, COS_C, -m.w * SIN_C);

    oii.x = fmaf(r.x, SIN_C, m.x * COS_C);
    oii.y = fmaf(r.y, SIN_C, m.y * COS_C);
    oii.z = fmaf(r.z, SIN_C, m.z * COS_C);
    oii.w = fmaf(r.w, SIN_C, m.w * COS_C);

    yr[i] = orr;
    yi[i] = oii;
}

// Fallback with bounds check, used only if n is not a clean multiple.
__global__ void __launch_bounds__(128, 16)
freq_shift_kernel_guard(const float4* __restrict__ xr,
                        const float4* __restrict__ xi,
                        float4* __restrict__ yr,
                        float4* __restrict__ yi,
                        int n4)
{
    int i = blockIdx.x * blockDim.x + threadIdx.x;
    if (i >= n4) return;

    float4 r = xr[i];
    float4 m = xi[i];

    float4 orr, oii;
    orr.x = fmaf(r.x, COS_C, -m.x * SIN_C);
    orr.y = fmaf(r.y, COS_C, -m.y * SIN_C);
    orr.z = fmaf(r.z, COS_C, -m.z * SIN_C);
    orr.w = fmaf(r.w, COS_C, -m.w * SIN_C);

    oii.x = fmaf(r.x, SIN_C, m.x * COS_C);
    oii.y = fmaf(r.y, SIN_C, m.y * COS_C);
    oii.z = fmaf(r.z, SIN_C, m.z * COS_C);
    oii.w = fmaf(r.w, SIN_C, m.w * COS_C);

    yr[i] = orr;
    yi[i] = oii;
}

extern "C" void kernel_launch(void* const* d_in, const int* in_sizes, int n_in,
                              void* d_out, int out_size)
{
    const float* x_real = (const float*)d_in[0];
    const float* x_imag = (const float*)d_in[1];
    float* out = (float*)d_out;

    const int n = in_sizes[0];          // B*M*N = 33,554,432
    const int n4 = n / 4;

    float* out_real = out;
    float* out_imag = out + n;

    const int threads = 128;

    if ((n % (4 * threads)) == 0) {
        const int blocks = n4 / threads;   // exact tiling, no guard
        freq_shift_kernel<<<blocks, threads>>>(
            (const float4*)x_real, (const float4*)x_imag,
            (float4*)out_real, (float4*)out_imag);
    } else {
        const int blocks = (n4 + threads - 1) / threads;
        freq_shift_kernel_guard<<<blocks, threads>>>(
            (const float4*)x_real, (const float4*)x_imag,
            (float4*)out_real, (float4*)out_imag, n4);
    }
}

// round 9
// speedup vs baseline: 1.0031x; 1.0031x over previous
#include <cuda_runtime.h>

// y = exp(i * LZ * DPHI) * x, elementwise.
// ifft2(fft2(x) * scalar) == scalar * x by linearity of the FFT.
// LZ*DPHI = 0.05 -> c = cos(0.05) + i*sin(0.05)
//
// Inputs:  d_in[0] = x_real [B*M*N] f32, d_in[1] = x_imag [B*M*N] f32
// Output:  d_out [2*B*M*N] f32, first half = real(y), second half = imag(y)
//
// FINAL CONVERGED KERNEL. Pure HBM-bound stream (256 MB read + 256 MB write,
// zero reuse, information-theoretic minimum traffic) sustained at 6.53 TB/s =
// the measured B300 mixed 50/50 R/W DRAM ceiling (82.5% of 8 TB/s spec;
// remainder is bus turnaround, not kernel-addressable).
// Search exhausted: block sweep 64/128/256/512 (convex, 128 optimal),
// MLP depth, .cs cache policies, persistence, guard elimination.

#define COS_C 0.9987502603949663f
#define SIN_C 0.0499791692706783f

__global__ void __launch_bounds__(128, 16)
freq_shift_kernel(const float4* __restrict__ xr,
                  const float4* __restrict__ xi,
                  float4* __restrict__ yr,
                  float4* __restrict__ yi)
{
    int i = blockIdx.x * blockDim.x + threadIdx.x;

    float4 r = xr[i];
    float4 m = xi[i];

    float4 orr, oii;
    orr.x = fmaf(r.x, COS_C, -m.x * SIN_C);
    orr.y = fmaf(r.y, COS_C, -m.y * SIN_C);
    orr.z = fmaf(r.z, COS_C, -m.z * SIN_C);
    orr.w = fmaf(r.w, COS_C, -m.w * SIN_C);

    oii.x = fmaf(r.x, SIN_C, m.x * COS_C);
    oii.y = fmaf(r.y, SIN_C, m.y * COS_C);
    oii.z = fmaf(r.z, SIN_C, m.z * COS_C);
    oii.w = fmaf(r.w, SIN_C, m.w * COS_C);

    yr[i] = orr;
    yi[i] = oii;
}

// Fallback with bounds check, used only if n is not a clean multiple of 512.
__global__ void __launch_bounds__(128, 16)
freq_shift_kernel_guard(const float4* __restrict__ xr,
                        const float4* __restrict__ xi,
                        float4* __restrict__ yr,
                        float4* __restrict__ yi,
                        int n4)
{
    int i = blockIdx.x * blockDim.x + threadIdx.x;
    if (i >= n4) return;

    float4 r = xr[i];
    float4 m = xi[i];

    float4 orr, oii;
    orr.x = fmaf(r.x, COS_C, -m.x * SIN_C);
    orr.y = fmaf(r.y, COS_C, -m.y * SIN_C);
    orr.z = fmaf(r.z, COS_C, -m.z * SIN_C);
    orr.w = fmaf(r.w, COS_C, -m.w * SIN_C);

    oii.x = fmaf(r.x, SIN_C, m.x * COS_C);
    oii.y = fmaf(r.y, SIN_C, m.y * COS_C);
    oii.z = fmaf(r.z, SIN_C, m.z * COS_C);
    oii.w = fmaf(r.w, SIN_C, m.w * COS_C);

    yr[i] = orr;
    yi[i] = oii;
}

extern "C" void kernel_launch(void* const* d_in, const int* in_sizes, int n_in,
                              void* d_out, int out_size)
{
    const float* x_real = (const float*)d_in[0];
    const float* x_imag = (const float*)d_in[1];
    float* out = (float*)d_out;

    const int n = in_sizes[0];          // B*M*N = 33,554,432
    const int n4 = n / 4;

    float* out_real = out;
    float* out_imag = out + n;

    const int threads = 128;

    if ((n % (4 * threads)) == 0) {
        const int blocks = n4 / threads;   // exact tiling, no guard
        freq_shift_kernel<<<blocks, threads>>>(
            (const float4*)x_real, (const float4*)x_imag,
            (float4*)out_real, (float4*)out_imag);
    } else {
        const int blocks = (n4 + threads - 1) / threads;
        freq_shift_kernel_guard<<<blocks, threads>>>(
            (const float4*)x_real, (const float4*)x_imag,
            (float4*)out_real, (float4*)out_imag, n4);
    }
}

// round 10
// speedup vs baseline: 1.0067x; 1.0035x over previous
#include <cuda_runtime.h>

// y = exp(i * LZ * DPHI) * x, elementwise.
// ifft2(fft2(x) * scalar) == scalar * x by linearity of the FFT.
// LZ*DPHI = 0.05 -> c = cos(0.05) + i*sin(0.05)
//
// Inputs:  d_in[0] = x_real [B*M*N] f32, d_in[1] = x_imag [B*M*N] f32
// Output:  d_out [2*B*M*N] f32, first half = real(y), second half = imag(y)
//
// FINAL CONVERGED KERNEL. Pure HBM-bound stream (256 MB read + 256 MB write,
// zero reuse, information-theoretic minimum traffic) sustained at ~6.5 TB/s =
// the measured B300 mixed 50/50 R/W DRAM ceiling (~82% of 8 TB/s spec;
// remainder is bus turnaround, not kernel-addressable).
// Search exhausted over 9 rounds: block sweep 64/128/256/512 (convex, 128
// optimal), MLP depth 2 vs 4 (neutral), .cs cache policies on loads/stores/
// both (neutral), persistent grid-stride (regressed), guard elimination
// (alu pipe 0.6% -> 0.0%).

#define COS_C 0.9987502603949663f
#define SIN_C 0.0499791692706783f

__global__ void __launch_bounds__(128, 16)
freq_shift_kernel(const float4* __restrict__ xr,
                  const float4* __restrict__ xi,
                  float4* __restrict__ yr,
                  float4* __restrict__ yi)
{
    int i = blockIdx.x * blockDim.x + threadIdx.x;

    float4 r = xr[i];
    float4 m = xi[i];

    float4 orr, oii;
    orr.x = fmaf(r.x, COS_C, -m.x * SIN_C);
    orr.y = fmaf(r.y, COS_C, -m.y * SIN_C);
    orr.z = fmaf(r.z, COS_C, -m.z * SIN_C);
    orr.w = fmaf(r.w, COS_C, -m.w * SIN_C);

    oii.x = fmaf(r.x, SIN_C, m.x * COS_C);
    oii.y = fmaf(r.y, SIN_C, m.y * COS_C);
    oii.z = fmaf(r.z, SIN_C, m.z * COS_C);
    oii.w = fmaf(r.w, SIN_C, m.w * COS_C);

    yr[i] = orr;
    yi[i] = oii;
}

// Fallback with bounds check, used only if n is not a clean multiple of 512.
__global__ void __launch_bounds__(128, 16)
freq_shift_kernel_guard(const float4* __restrict__ xr,
                        const float4* __restrict__ xi,
                        float4* __restrict__ yr,
                        float4* __restrict__ yi,
                        int n4)
{
    int i = blockIdx.x * blockDim.x + threadIdx.x;
    if (i >= n4) return;

    float4 r = xr[i];
    float4 m = xi[i];

    float4 orr, oii;
    orr.x = fmaf(r.x, COS_C, -m.x * SIN_C);
    orr.y = fmaf(r.y, COS_C, -m.y * SIN_C);
    orr.z = fmaf(r.z, COS_C, -m.z * SIN_C);
    orr.w = fmaf(r.w, COS_C, -m.w * SIN_C);

    oii.x = fmaf(r.x, SIN_C, m.x * COS_C);
    oii.y = fmaf(r.y, SIN_C, m.y * COS_C);
    oii.z = fmaf(r.z, SIN_C, m.z * COS_C);
    oii.w = fmaf(r.w, SIN_C, m.w * COS_C);

    yr[i] = orr;
    yi[i] = oii;
}

extern "C" void kernel_launch(void* const* d_in, const int* in_sizes, int n_in,
                              void* d_out, int out_size)
{
    const float* x_real = (const float*)d_in[0];
    const float* x_imag = (const float*)d_in[1];
    float* out = (float*)d_out;

    const int n = in_sizes[0];          // B*M*N = 33,554,432
    const int n4 = n / 4;

    float* out_real = out;
    float* out_imag = out + n;

    const int threads = 128;

    if ((n % (4 * threads)) == 0) {
        const int blocks = n4 / threads;   // exact tiling, no guard
        freq_shift_kernel<<<blocks, threads>>>(
            (const float4*)x_real, (const float4*)x_imag,
            (float4*)out_real, (float4*)out_imag);
    } else {
        const int blocks = (n4 + threads - 1) / threads;
        freq_shift_kernel_guard<<<blocks, threads>>>(
            (const float4*)x_real, (const float4*)x_imag,
            (float4*)out_real, (float4*)out_imag, n4);
    }
}